// round 15
// baseline (speedup 1.0000x reference)
#include <cuda_runtime.h>
#include <cstdint>

#define D          512
#define ROW_BYTES  2048
#define MARGIN     1.0f
#define NSTAGE     2
#define WPB        4                  // warps per block
#define TPB        (WPB * 32)
#define GRID       512
#define ITERS      8                  // triplets per warp: 512*4*8 = 16384
#define STAGE_TX   (2 * ROW_BYTES)    // A + P rows via TMA (N via LDG)

__global__ void zero_out_kernel(float* out) {
    if (threadIdx.x == 0) out[0] = 0.0f;
}

__device__ __forceinline__ uint32_t smem_u32(const void* p) {
    return (uint32_t)__cvta_generic_to_shared(p);
}
__device__ __forceinline__ void mbar_init(uint32_t addr, uint32_t count) {
    asm volatile("mbarrier.init.shared::cta.b64 [%0], %1;" :: "r"(addr), "r"(count) : "memory");
}
__device__ __forceinline__ void mbar_expect_tx(uint32_t addr, uint32_t bytes) {
    asm volatile("mbarrier.arrive.expect_tx.shared::cta.b64 _, [%0], %1;"
                 :: "r"(addr), "r"(bytes) : "memory");
}
__device__ __forceinline__ void mbar_wait(uint32_t addr, uint32_t parity) {
    uint32_t done = 0;
    while (!done) {
        asm volatile(
            "{\n\t.reg .pred p;\n\t"
            "mbarrier.try_wait.parity.acquire.cta.shared::cta.b64 p, [%1], %2, 0x989680;\n\t"
            "selp.b32 %0, 1, 0, p;\n\t}"
            : "=r"(done) : "r"(addr), "r"(parity) : "memory");
    }
}
__device__ __forceinline__ void bulk_g2s(uint32_t dst_smem, const void* src_gmem,
                                         uint32_t bytes, uint32_t mbar) {
    asm volatile(
        "cp.async.bulk.shared::cluster.global.mbarrier::complete_tx::bytes "
        "[%0], [%1], %2, [%3];"
        :: "r"(dst_smem), "l"(src_gmem), "r"(bytes), "r"(mbar) : "memory");
}
__device__ __forceinline__ void fma2(unsigned long long& acc,
                                     unsigned long long a,
                                     unsigned long long b) {
    asm("fma.rn.f32x2 %0, %1, %2, %0;" : "+l"(acc) : "l"(a), "l"(b));
}
__device__ __forceinline__ float lo_f(unsigned long long v) {
    return __uint_as_float((unsigned)(v & 0xFFFFFFFFull));
}
__device__ __forceinline__ float hi_f(unsigned long long v) {
    return __uint_as_float((unsigned)(v >> 32));
}

__global__ void __launch_bounds__(TPB)
triplet_split_path_kernel(const float* __restrict__ batch,
                          const int* __restrict__ triplets,
                          float* __restrict__ out) {
    // Dynamic smem: rows[WPB][NSTAGE][2][D] floats = 32768 bytes.
    extern __shared__ __align__(1024) float rows[];
    __shared__ __align__(8) unsigned long long full_bar[WPB][NSTAGE];
    __shared__ int   idx_s[WPB][ITERS * 3];
    __shared__ float warp_part[WPB];

    const int tid  = threadIdx.x;
    const int lane = tid & 31;
    const int wid  = tid >> 5;
    const int wg   = blockIdx.x * WPB + wid;   // global warp id

    // This warp's 8 triplets (24 indices) -> smem.
    if (lane < ITERS * 3)
        idx_s[wid][lane] = triplets[wg * (ITERS * 3) + lane];

    if (tid < WPB * NSTAGE)
        mbar_init(smem_u32(&full_bar[tid >> 1][tid & 1]), 1);
    if (tid == 0)
        asm volatile("fence.proxy.async.shared::cta;" ::: "memory");
    __syncthreads();

    #define SLOT(w, s, r) (rows + (((w) * NSTAGE + (s)) * 2 + (r)) * D)
    #define NROW(t) (reinterpret_cast<const ulonglong2*>( \
                        batch + (size_t)idx_s[wid][(t) * 3 + 2] * D) + lane)

    // Prologue: TMA fills A,P for stages 0,1; LDG fills N for triplets 0,1.
    if (lane == 0) {
        #pragma unroll
        for (int s = 0; s < NSTAGE; s++) {
            const uint32_t fb = smem_u32(&full_bar[wid][s]);
            mbar_expect_tx(fb, STAGE_TX);
            #pragma unroll
            for (int r = 0; r < 2; r++) {
                const int idx = idx_s[wid][s * 3 + r];
                bulk_g2s(smem_u32(SLOT(wid, s, r)),
                         batch + (size_t)idx * D, ROW_BYTES, fb);
            }
        }
    }

    // Register double buffer for N rows: nbuf[i&1] holds triplet i's N row.
    ulonglong2 nbuf[2][4];
    {
        const ulonglong2* N0 = NROW(0);
        const ulonglong2* N1 = NROW(1);
        #pragma unroll
        for (int j = 0; j < 4; j++) nbuf[0][j] = N0[j * 32];
        #pragma unroll
        for (int j = 0; j < 4; j++) nbuf[1][j] = N1[j * 32];
    }

    float acc = 0.0f;  // lane-0 accumulator

    #pragma unroll
    for (int i = 0; i < ITERS; i++) {
        const int s  = i & 1;
        const int ph = (i >> 1) & 1;

        mbar_wait(smem_u32(&full_bar[wid][s]), ph);

        const ulonglong2* A = reinterpret_cast<const ulonglong2*>(SLOT(wid, s, 0)) + lane;
        const ulonglong2* P = reinterpret_cast<const ulonglong2*>(SLOT(wid, s, 1)) + lane;

        // Drain stage s from smem into registers FIRST, so the refill can be
        // issued before the FMA chain and shuffle tree (~150-200 cyc earlier).
        ulonglong2 va[4], vp[4];
        #pragma unroll
        for (int j = 0; j < 4; j++) { va[j] = A[j * 32]; vp[j] = P[j * 32]; }

        // All lanes have issued their LDS of stage s; TMA refill data cannot
        // land in smem for >=300 cyc (L2 round trip), LDS retires in ~29 cyc.
        __syncwarp();
        if (i + NSTAGE < ITERS && lane == 0) {
            const int t = i + NSTAGE;
            const uint32_t fb = smem_u32(&full_bar[wid][s]);
            mbar_expect_tx(fb, STAGE_TX);
            #pragma unroll
            for (int r = 0; r < 2; r++) {
                const int idx = idx_s[wid][t * 3 + r];
                bulk_g2s(smem_u32(SLOT(wid, s, r)),
                         batch + (size_t)idx * D, ROW_BYTES, fb);
            }
        }

        // d_ap - d_an = Sp - Sn - 2*Sap + 2*San  (Sum a^2 cancels)
        unsigned long long Sp = 0, Sn = 0, Sap = 0, San = 0;
        #pragma unroll
        for (int j = 0; j < 4; j++) {
            const ulonglong2 a = va[j];
            const ulonglong2 p = vp[j];
            const ulonglong2 n = nbuf[s][j];
            fma2(Sp,  p.x, p.x);  fma2(Sp,  p.y, p.y);
            fma2(Sn,  n.x, n.x);  fma2(Sn,  n.y, n.y);
            fma2(Sap, a.x, p.x);  fma2(Sap, a.y, p.y);
            fma2(San, a.x, n.x);  fma2(San, a.y, n.y);
        }

        // LDG-prefetch N row for triplet i+2 into the buffer just freed.
        if (i + NSTAGE < ITERS) {
            const ulonglong2* NN = NROW(i + NSTAGE);
            #pragma unroll
            for (int j = 0; j < 4; j++) nbuf[s][j] = NN[j * 32];
        }

        float v = (lo_f(Sp) + hi_f(Sp)) - (lo_f(Sn) + hi_f(Sn))
                + 2.0f * ((lo_f(San) + hi_f(San)) - (lo_f(Sap) + hi_f(Sap)));

        #pragma unroll
        for (int off = 16; off > 0; off >>= 1)
            v += __shfl_down_sync(0xFFFFFFFFu, v, off);

        if (lane == 0) acc += fmaxf(v + MARGIN, 0.0f);
    }

    if (lane == 0) warp_part[wid] = acc;
    __syncthreads();
    if (tid == 0) {
        float total = 0.0f;
        #pragma unroll
        for (int w = 0; w < WPB; w++) total += warp_part[w];
        atomicAdd(out, total);
    }
    #undef SLOT
    #undef NROW
}

extern "C" void kernel_launch(void* const* d_in, const int* in_sizes, int n_in,
                              void* d_out, int out_size) {
    const float* batch    = (const float*)d_in[0];
    const int*   triplets = (const int*)d_in[1];
    float* out = (float*)d_out;

    const int smem_bytes = WPB * NSTAGE * 2 * D * sizeof(float);  // 32768
    static bool attr_set = false;
    if (!attr_set) {
        cudaFuncSetAttribute(triplet_split_path_kernel,
                             cudaFuncAttributeMaxDynamicSharedMemorySize, smem_bytes);
        attr_set = true;
    }

    zero_out_kernel<<<1, 32>>>(out);
    triplet_split_path_kernel<<<GRID, TPB, smem_bytes>>>(batch, triplets, out);
}

// round 16
// speedup vs baseline: 1.0355x; 1.0355x over previous
#include <cuda_runtime.h>
#include <cstdint>

#define D          512
#define ROW_BYTES  2048
#define MARGIN     1.0f
#define NSTAGE     2
#define WPB        4                  // warps per block
#define TPB        (WPB * 32)
#define GRID       512
#define ITERS      8                  // triplets per warp: 512*4*8 = 16384
#define STAGE_TX   (2 * ROW_BYTES)    // A + P rows via TMA (N via LDG)

__global__ void zero_out_kernel(float* out) {
    if (threadIdx.x == 0) out[0] = 0.0f;
    // Signal completion early so the PDL-dependent main kernel's gated tail
    // can proceed as soon as the store is visible.
    cudaTriggerProgrammaticLaunchCompletion();
}

__device__ __forceinline__ uint32_t smem_u32(const void* p) {
    return (uint32_t)__cvta_generic_to_shared(p);
}
__device__ __forceinline__ void mbar_init(uint32_t addr, uint32_t count) {
    asm volatile("mbarrier.init.shared::cta.b64 [%0], %1;" :: "r"(addr), "r"(count) : "memory");
}
__device__ __forceinline__ void mbar_expect_tx(uint32_t addr, uint32_t bytes) {
    asm volatile("mbarrier.arrive.expect_tx.shared::cta.b64 _, [%0], %1;"
                 :: "r"(addr), "r"(bytes) : "memory");
}
__device__ __forceinline__ void mbar_wait(uint32_t addr, uint32_t parity) {
    uint32_t done = 0;
    while (!done) {
        asm volatile(
            "{\n\t.reg .pred p;\n\t"
            "mbarrier.try_wait.parity.acquire.cta.shared::cta.b64 p, [%1], %2, 0x989680;\n\t"
            "selp.b32 %0, 1, 0, p;\n\t}"
            : "=r"(done) : "r"(addr), "r"(parity) : "memory");
    }
}
__device__ __forceinline__ void bulk_g2s(uint32_t dst_smem, const void* src_gmem,
                                         uint32_t bytes, uint32_t mbar) {
    asm volatile(
        "cp.async.bulk.shared::cluster.global.mbarrier::complete_tx::bytes "
        "[%0], [%1], %2, [%3];"
        :: "r"(dst_smem), "l"(src_gmem), "r"(bytes), "r"(mbar) : "memory");
}
__device__ __forceinline__ void fma2(unsigned long long& acc,
                                     unsigned long long a,
                                     unsigned long long b) {
    asm("fma.rn.f32x2 %0, %1, %2, %0;" : "+l"(acc) : "l"(a), "l"(b));
}
__device__ __forceinline__ float lo_f(unsigned long long v) {
    return __uint_as_float((unsigned)(v & 0xFFFFFFFFull));
}
__device__ __forceinline__ float hi_f(unsigned long long v) {
    return __uint_as_float((unsigned)(v >> 32));
}

__global__ void __launch_bounds__(TPB)
triplet_split_path_kernel(const float* __restrict__ batch,
                          const int* __restrict__ triplets,
                          float* __restrict__ out) {
    // Dynamic smem: rows[WPB][NSTAGE][2][D] floats = 32768 bytes.
    extern __shared__ __align__(1024) float rows[];
    __shared__ __align__(8) unsigned long long full_bar[WPB][NSTAGE];
    __shared__ int   idx_s[WPB][ITERS * 3];
    __shared__ float warp_part[WPB];

    const int tid  = threadIdx.x;
    const int lane = tid & 31;
    const int wid  = tid >> 5;
    const int wg   = blockIdx.x * WPB + wid;   // global warp id

    // This warp's 8 triplets (24 indices) -> smem.
    if (lane < ITERS * 3)
        idx_s[wid][lane] = triplets[wg * (ITERS * 3) + lane];

    if (tid < WPB * NSTAGE)
        mbar_init(smem_u32(&full_bar[tid >> 1][tid & 1]), 1);
    if (tid == 0)
        asm volatile("fence.proxy.async.shared::cta;" ::: "memory");
    __syncthreads();

    #define SLOT(w, s, r) (rows + (((w) * NSTAGE + (s)) * 2 + (r)) * D)
    #define NROW(t) (reinterpret_cast<const ulonglong2*>( \
                        batch + (size_t)idx_s[wid][(t) * 3 + 2] * D) + lane)

    // Prologue: TMA fills A,P for stages 0,1; LDG fills N for triplets 0,1.
    if (lane == 0) {
        #pragma unroll
        for (int s = 0; s < NSTAGE; s++) {
            const uint32_t fb = smem_u32(&full_bar[wid][s]);
            mbar_expect_tx(fb, STAGE_TX);
            #pragma unroll
            for (int r = 0; r < 2; r++) {
                const int idx = idx_s[wid][s * 3 + r];
                bulk_g2s(smem_u32(SLOT(wid, s, r)),
                         batch + (size_t)idx * D, ROW_BYTES, fb);
            }
        }
    }

    // Register double buffer for N rows: nbuf[i&1] holds triplet i's N row.
    ulonglong2 nbuf[2][4];
    {
        const ulonglong2* N0 = NROW(0);
        const ulonglong2* N1 = NROW(1);
        #pragma unroll
        for (int j = 0; j < 4; j++) nbuf[0][j] = N0[j * 32];
        #pragma unroll
        for (int j = 0; j < 4; j++) nbuf[1][j] = N1[j * 32];
    }

    float acc = 0.0f;  // lane-0 accumulator

    #pragma unroll
    for (int i = 0; i < ITERS; i++) {
        const int s  = i & 1;
        const int ph = (i >> 1) & 1;

        mbar_wait(smem_u32(&full_bar[wid][s]), ph);

        const ulonglong2* A = reinterpret_cast<const ulonglong2*>(SLOT(wid, s, 0)) + lane;
        const ulonglong2* P = reinterpret_cast<const ulonglong2*>(SLOT(wid, s, 1)) + lane;

        // Drain stage s from smem into registers first, so the refill is
        // issued before the FMA chain and shuffle tree.
        ulonglong2 va[4], vp[4];
        #pragma unroll
        for (int j = 0; j < 4; j++) { va[j] = A[j * 32]; vp[j] = P[j * 32]; }

        __syncwarp();
        if (i + NSTAGE < ITERS && lane == 0) {
            const int t = i + NSTAGE;
            const uint32_t fb = smem_u32(&full_bar[wid][s]);
            mbar_expect_tx(fb, STAGE_TX);
            #pragma unroll
            for (int r = 0; r < 2; r++) {
                const int idx = idx_s[wid][t * 3 + r];
                bulk_g2s(smem_u32(SLOT(wid, s, r)),
                         batch + (size_t)idx * D, ROW_BYTES, fb);
            }
        }

        // d_ap - d_an = Sp - Sn - 2*Sap + 2*San  (Sum a^2 cancels)
        unsigned long long Sp = 0, Sn = 0, Sap = 0, San = 0;
        #pragma unroll
        for (int j = 0; j < 4; j++) {
            const ulonglong2 a = va[j];
            const ulonglong2 p = vp[j];
            const ulonglong2 n = nbuf[s][j];
            fma2(Sp,  p.x, p.x);  fma2(Sp,  p.y, p.y);
            fma2(Sn,  n.x, n.x);  fma2(Sn,  n.y, n.y);
            fma2(Sap, a.x, p.x);  fma2(Sap, a.y, p.y);
            fma2(San, a.x, n.x);  fma2(San, a.y, n.y);
        }

        // LDG-prefetch N row for triplet i+2 into the buffer just freed.
        if (i + NSTAGE < ITERS) {
            const ulonglong2* NN = NROW(i + NSTAGE);
            #pragma unroll
            for (int j = 0; j < 4; j++) nbuf[s][j] = NN[j * 32];
        }

        float v = (lo_f(Sp) + hi_f(Sp)) - (lo_f(Sn) + hi_f(Sn))
                + 2.0f * ((lo_f(San) + hi_f(San)) - (lo_f(Sap) + hi_f(Sap)));

        #pragma unroll
        for (int off = 16; off > 0; off >>= 1)
            v += __shfl_down_sync(0xFFFFFFFFu, v, off);

        if (lane == 0) acc += fmaxf(v + MARGIN, 0.0f);
    }

    if (lane == 0) warp_part[wid] = acc;
    __syncthreads();
    if (tid == 0) {
        float total = 0.0f;
        #pragma unroll
        for (int w = 0; w < WPB; w++) total += warp_part[w];
        // PDL gate: wait for the zero-kernel (finished ~11us ago) before
        // the only access to `out` in this kernel.
        cudaGridDependencySynchronize();
        atomicAdd(out, total);
    }
    #undef SLOT
    #undef NROW
}

extern "C" void kernel_launch(void* const* d_in, const int* in_sizes, int n_in,
                              void* d_out, int out_size) {
    const float* batch    = (const float*)d_in[0];
    const int*   triplets = (const int*)d_in[1];
    float* out = (float*)d_out;

    const int smem_bytes = WPB * NSTAGE * 2 * D * sizeof(float);  // 32768
    static bool attr_set = false;
    if (!attr_set) {
        cudaFuncSetAttribute(triplet_split_path_kernel,
                             cudaFuncAttributeMaxDynamicSharedMemorySize, smem_bytes);
        attr_set = true;
    }

    zero_out_kernel<<<1, 32>>>(out);

    // Programmatic dependent launch: main kernel launches concurrently with
    // the zero kernel; only its tail (cudaGridDependencySynchronize) orders
    // against zero_out completion.
    cudaLaunchConfig_t cfg = {};
    cfg.gridDim  = dim3(GRID, 1, 1);
    cfg.blockDim = dim3(TPB, 1, 1);
    cfg.dynamicSmemBytes = smem_bytes;
    cfg.stream = 0;
    cudaLaunchAttribute attrs[1];
    attrs[0].id = cudaLaunchAttributeProgrammaticStreamSerialization;
    attrs[0].val.programmaticStreamSerializationAllowed = 1;
    cfg.attrs = attrs;
    cfg.numAttrs = 1;
    cudaLaunchKernelEx(&cfg, triplet_split_path_kernel, batch, triplets, out);
}